// round 16
// baseline (speedup 1.0000x reference)
#include <cuda_runtime.h>
#include <cuda_fp16.h>
#include <cstdint>

#define BATCH 16
#define RDIM 256
#define CDIM 256
#define NPIX (RDIM*CDIM)
#define F 64
#define M_TOTAL (BATCH*NPIX)   /* 1048576 rows */

// ---------------- scratch ----------------------------------------------------
// __device__ globals are zero-initialized at module load. g_sum/g_sumsq/g_ctr
// are reset by the LAST k_gemm CTA each launch -> deterministic across graph
// replays with no separate zeroing kernel.
__device__ __half g_Htp[(size_t)M_TOTAL * F];   // pre-BN linear output, fp16, 128MB
__device__ float g_sum[F];
__device__ float g_sumsq[F];
__device__ float g_scale[F];
__device__ float g_bias[F];
__device__ unsigned int g_ctr;

// ---------------- helpers ----------------------------------------------------
__device__ __forceinline__ uint32_t h2_bits(__half2 h) {
    uint32_t u;
    __builtin_memcpy(&u, &h, 4);
    return u;
}

__device__ __forceinline__ void cp_async16(void* smem_dst, const void* gsrc) {
    uint32_t s = (uint32_t)__cvta_generic_to_shared(smem_dst);
    asm volatile("cp.async.cg.shared.global [%0], [%1], 16;\n" :: "r"(s), "l"(gsrc));
}

// ---------------- K1: Ht = H @ W, fp16 mma, 2-stage cp.async pipeline --------
// CTA: 128 threads (4 warps). Each warp streams TPW tiles of 16 rows through a
// double-buffered fp32 staging area (cp.async, prefetch distance 1 tile).
// Consumed buffer is recycled as fp16 epilogue staging.
// TPW=16 (coarse): per-CTA prologue amortized — measured optimum.
// Tail: last-finishing CTA finalizes BN scale/bias (replaces k_stats launch).
// NOTE: strides MUST be >= 64 (k/col index spans 0..63); 72 additionally makes
// frag LDS.64, epilogue STS and the dense LDS.128 sweep all conflict-free.
#define TPW 16                      /* tiles (of 16 rows) per warp */
#define FSTRIDE 72                  /* floats */
#define WSTRIDE 72                  /* halves */

__global__ __launch_bounds__(128)
void k_gemm(const float* __restrict__ H, const float* __restrict__ W,
            const float* __restrict__ gamma, const float* __restrict__ beta) {
    __shared__ __half sWt[64 * WSTRIDE];          // 9.2KB
    __shared__ float sF[4][2][16 * FSTRIDE];      // 36.9KB
    __shared__ float sSum[F], sSq[F];
    __shared__ int sIsLast;

    const int tid  = threadIdx.x;
    const int warp = tid >> 5;
    const int lane = tid & 31;
    const int g    = lane >> 2;    // 0..7
    const int tg   = lane & 3;     // 0..3

    const size_t warpRow0 = ((size_t)blockIdx.x * 4 + warp) * (TPW * 16);

    auto stage = [&](int t, float* buf) {
        const float* src = H + (warpRow0 + (size_t)t * 16) * F;
#pragma unroll
        for (int r = 0; r < 8; r++) {
            int f   = lane + 32 * r;      // float4 chunk 0..127
            int row = f >> 4, c4 = f & 15;
            cp_async16(&buf[row * FSTRIDE + c4 * 4], src + (size_t)f * 4);
        }
        asm volatile("cp.async.commit_group;\n" ::);
    };

    // Kick off tile 0 before anything else
    stage(0, sF[warp][0]);

    if (tid < F) { sSum[tid] = 0.f; sSq[tid] = 0.f; }

    // Build Wt (fp16, transposed) in smem
    for (int idx = tid; idx < 64 * 64; idx += 128) {
        int k = idx >> 6, n = idx & 63;
        sWt[n * WSTRIDE + k] = __float2half(W[idx]);
    }
    __syncthreads();

    // Stat accumulators: cols (nt*8 + 2tg) and (+1)
    float s[8][2], q[8][2];
#pragma unroll
    for (int nt = 0; nt < 8; nt++) { s[nt][0] = s[nt][1] = q[nt][0] = q[nt][1] = 0.f; }

#pragma unroll 1
    for (int t = 0; t < TPW; t++) {
        float* buf = sF[warp][t & 1];
        if (t + 1 < TPW) {
            stage(t + 1, sF[warp][(t + 1) & 1]);
            asm volatile("cp.async.wait_group 1;\n" ::);
        } else {
            asm volatile("cp.async.wait_group 0;\n" ::);
        }
        __syncwarp();   // staged data visible warp-wide

        float acc[8][4];
#pragma unroll
        for (int nt = 0; nt < 8; nt++)
#pragma unroll
            for (int i = 0; i < 4; i++) acc[nt][i] = 0.f;

#pragma unroll
        for (int ks = 0; ks < 4; ks++) {
            const int kc = ks * 16 + 2 * tg;
            float2 f0 = *(const float2*)&buf[(g    ) * FSTRIDE + kc    ];
            float2 f1 = *(const float2*)&buf[(g + 8) * FSTRIDE + kc    ];
            float2 f2 = *(const float2*)&buf[(g    ) * FSTRIDE + kc + 8];
            float2 f3 = *(const float2*)&buf[(g + 8) * FSTRIDE + kc + 8];
            uint32_t a0 = h2_bits(__floats2half2_rn(f0.x, f0.y));
            uint32_t a1 = h2_bits(__floats2half2_rn(f1.x, f1.y));
            uint32_t a2 = h2_bits(__floats2half2_rn(f2.x, f2.y));
            uint32_t a3 = h2_bits(__floats2half2_rn(f3.x, f3.y));
#pragma unroll
            for (int nt = 0; nt < 8; nt++) {
                uint32_t b0 = *(const uint32_t*)&sWt[(nt * 8 + g) * WSTRIDE + kc    ];
                uint32_t b1 = *(const uint32_t*)&sWt[(nt * 8 + g) * WSTRIDE + kc + 8];
                asm volatile(
                    "mma.sync.aligned.m16n8k16.row.col.f32.f16.f16.f32 "
                    "{%0,%1,%2,%3}, {%4,%5,%6,%7}, {%8,%9}, {%0,%1,%2,%3};"
                    : "+f"(acc[nt][0]), "+f"(acc[nt][1]),
                      "+f"(acc[nt][2]), "+f"(acc[nt][3])
                    : "r"(a0), "r"(a1), "r"(a2), "r"(a3),
                      "r"(b0), "r"(b1));
            }
        }
        __syncwarp();   // fragment reads done; buffer can be recycled

        // Epilogue: stats + fp16 fragments -> recycled staging buffer
        __half* eb = (__half*)buf;
#pragma unroll
        for (int nt = 0; nt < 8; nt++) {
            int colb = nt * 8 + 2 * tg;
            float c0 = acc[nt][0], c1 = acc[nt][1];
            float c2 = acc[nt][2], c3 = acc[nt][3];
            *(__half2*)&eb[(g    ) * WSTRIDE + colb] = __floats2half2_rn(c0, c1);
            *(__half2*)&eb[(g + 8) * WSTRIDE + colb] = __floats2half2_rn(c2, c3);
            s[nt][0] += c0 + c2;           s[nt][1] += c1 + c3;
            q[nt][0] += c0 * c0 + c2 * c2; q[nt][1] += c1 * c1 + c3 * c3;
        }
        __syncwarp();

        // Dense store: 4 x (LDS.128 + STG.128) covering 16 rows x 128B
        __half* outp = g_Htp + (warpRow0 + (size_t)t * 16) * F;
#pragma unroll
        for (int r = 0; r < 4; r++) {
            int u   = lane + 32 * r;        // 16B unit index, 128 total
            int row = u >> 3, cu = u & 7;
            uint4 x = *(const uint4*)&eb[row * WSTRIDE + cu * 8];
            *(uint4*)&outp[(size_t)row * F + cu * 8] = x;
        }
        __syncwarp();   // epilogue reads done before cp.async refills this buffer
    }

    // Reduce stats: butterfly over g, smem atomics, 64 global atomics
#pragma unroll
    for (int off = 4; off < 32; off <<= 1) {
#pragma unroll
        for (int nt = 0; nt < 8; nt++) {
            s[nt][0] += __shfl_xor_sync(0xffffffffu, s[nt][0], off);
            s[nt][1] += __shfl_xor_sync(0xffffffffu, s[nt][1], off);
            q[nt][0] += __shfl_xor_sync(0xffffffffu, q[nt][0], off);
            q[nt][1] += __shfl_xor_sync(0xffffffffu, q[nt][1], off);
        }
    }
    if (lane < 4) {
#pragma unroll
        for (int nt = 0; nt < 8; nt++) {
            int c = nt * 8 + 2 * lane;
            atomicAdd(&sSum[c],     s[nt][0]);
            atomicAdd(&sSum[c + 1], s[nt][1]);
            atomicAdd(&sSq[c],      q[nt][0]);
            atomicAdd(&sSq[c + 1],  q[nt][1]);
        }
    }
    __syncthreads();
    if (tid < F) {
        atomicAdd(&g_sum[tid],   sSum[tid]);
        atomicAdd(&g_sumsq[tid], sSq[tid]);
    }

    // ---- last-CTA finalization (threadfence-reduction pattern) ----
    __threadfence();
    __syncthreads();
    if (tid == 0) {
        unsigned int c = atomicAdd(&g_ctr, 1u);
        sIsLast = (c == gridDim.x - 1);
    }
    __syncthreads();
    if (sIsLast && tid < F) {
        float sum = __ldcg(&g_sum[tid]);      // L2-coherent reads (bypass L1)
        float sq  = __ldcg(&g_sumsq[tid]);
        float inv_m = 1.f / (float)M_TOTAL;
        float mean = sum * inv_m;
        float var  = sq * inv_m - mean * mean;
        float is   = rsqrtf(var + 1e-5f);
        float sc   = gamma[tid] * is;
        g_scale[tid] = sc;
        g_bias[tid]  = beta[tid] - mean * sc;
        // Reset accumulators + counter for the next launch / graph replay
        g_sum[tid]   = 0.f;
        g_sumsq[tid] = 0.f;
        if (tid == 0) g_ctr = 0u;
    }
}

// ---------------- K3: BN + ReLU + normalized 3x3 stencil (fp16 in) -----------
// CTA: 288 threads = 18 cols (16 out + 2 halo) x 16 half4 chunks.
// Row tile = 16 (measured best); 2 output rows per __syncthreads (4 smem
// buffers), loads prefetched 2 ahead; dval hoisted.
__global__ __launch_bounds__(288, 4)
void k_stencil(float* __restrict__ out) {
    __shared__ float4 cs[4][18][16];

    const int tid   = threadIdx.x;
    const int chunk = tid & 15;      // 0..15 (4 channels each)
    const int colL  = tid >> 4;      // 0..17
    const int b     = blockIdx.z;
    const int j0    = blockIdx.x * 16;
    const int i0    = blockIdx.y * 16;
    const int j     = j0 - 1 + colL;
    const bool jin  = (j >= 0 && j < CDIM);
    const bool isOut = (colL >= 1 && colL <= 16);

    const int   rj  = 3 - (j == 0) - (j == CDIM - 1);
    const float d3v = rsqrtf(3.f * rj + 1e-5f);
    const float d2v = rsqrtf(2.f * rj + 1e-5f);

    const float4 sc = *(const float4*)&g_scale[chunk * 4];
    const float4 bs = *(const float4*)&g_bias[chunk * 4];
    const __half* base = g_Htp + (size_t)b * NPIX * F;

    auto dsel = [&](int i) -> float {
        return (i == 0 || i == RDIM - 1) ? d2v : d3v;
    };
    auto rawload = [&](int i) -> uint2 {
        if (!jin || i < 0 || i >= RDIM) return make_uint2(0u, 0u);
        return *(const uint2*)&base[((size_t)i * CDIM + j) * F + chunk * 4];
    };
    auto bnrow = [&](uint2 rw, int i) -> float4 {
        if (!jin || i < 0 || i >= RDIM) return make_float4(0.f, 0.f, 0.f, 0.f);
        float2 f0 = __half22float2(*(__half2*)&rw.x);
        float2 f1 = __half22float2(*(__half2*)&rw.y);
        float d = dsel(i);
        float4 r;
        r.x = fmaxf(fmaf(f0.x, sc.x, bs.x), 0.f) * d;
        r.y = fmaxf(fmaf(f0.y, sc.y, bs.y), 0.f) * d;
        r.z = fmaxf(fmaf(f1.x, sc.z, bs.z), 0.f) * d;
        r.w = fmaxf(fmaf(f1.y, sc.w, bs.w), 0.f) * d;
        return r;
    };

    float4 p = bnrow(rawload(i0 - 1), i0 - 1);
    float4 c = bnrow(rawload(i0), i0);
    uint2 rn  = rawload(i0 + 1);
    uint2 rn2 = rawload(i0 + 2);
    int bb = 0;

    for (int r = 0; r < 8; r++) {
        const int i = i0 + 2 * r;
        uint2 rn3 = rawload(i + 3);
        uint2 rn4 = rawload(i + 4);
        float4 n  = bnrow(rn,  i + 1);
        float4 n2 = bnrow(rn2, i + 2);
        float4 v0, v1;
        v0.x = p.x + c.x + n.x;   v1.x = c.x + n.x + n2.x;
        v0.y = p.y + c.y + n.y;   v1.y = c.y + n.y + n2.y;
        v0.z = p.z + c.z + n.z;   v1.z = c.z + n.z + n2.z;
        v0.w = p.w + c.w + n.w;   v1.w = c.w + n.w + n2.w;
        cs[bb][colL][chunk]     = v0;
        cs[bb + 1][colL][chunk] = v1;
        __syncthreads();
        if (isOut) {
            float4 l0 = cs[bb][colL - 1][chunk];
            float4 r0 = cs[bb][colL + 1][chunk];
            float dc0 = dsel(i);
            float4 o0;
            o0.x = (l0.x + v0.x + r0.x) * dc0;
            o0.y = (l0.y + v0.y + r0.y) * dc0;
            o0.z = (l0.z + v0.z + r0.z) * dc0;
            o0.w = (l0.w + v0.w + r0.w) * dc0;
            *(float4*)&out[((size_t)b * NPIX + (size_t)i * CDIM + j) * F + chunk * 4] = o0;

            float4 l1 = cs[bb + 1][colL - 1][chunk];
            float4 r1 = cs[bb + 1][colL + 1][chunk];
            float dc1 = dsel(i + 1);
            float4 o1;
            o1.x = (l1.x + v1.x + r1.x) * dc1;
            o1.y = (l1.y + v1.y + r1.y) * dc1;
            o1.z = (l1.z + v1.z + r1.z) * dc1;
            o1.w = (l1.w + v1.w + r1.w) * dc1;
            *(float4*)&out[((size_t)b * NPIX + (size_t)(i + 1) * CDIM + j) * F + chunk * 4] = o1;
        }
        p = n; c = n2; rn = rn3; rn2 = rn4; bb ^= 2;
    }
}

// ---------------- launch ------------------------------------------------------
extern "C" void kernel_launch(void* const* d_in, const int* in_sizes, int n_in,
                              void* d_out, int out_size) {
    (void)in_sizes; (void)n_in; (void)out_size;
    const float* H     = (const float*)d_in[0];
    const float* W     = (const float*)d_in[1];
    const float* gamma = (const float*)d_in[2];
    const float* beta  = (const float*)d_in[3];
    float* out = (float*)d_out;

    const int rows_per_cta = 4 * TPW * 16;   // 1024
    k_gemm<<<M_TOTAL / rows_per_cta, 128>>>(H, W, gamma, beta);
    dim3 g3(CDIM / 16, RDIM / 16, BATCH);
    k_stencil<<<g3, 288>>>(out);
}

// round 17
// speedup vs baseline: 1.0017x; 1.0017x over previous
#include <cuda_runtime.h>
#include <cuda_fp16.h>
#include <cstdint>

#define BATCH 16
#define RDIM 256
#define CDIM 256
#define NPIX (RDIM*CDIM)
#define F 64
#define M_TOTAL (BATCH*NPIX)   /* 1048576 rows */

// ---------------- scratch ----------------------------------------------------
// __device__ globals are zero-initialized at module load. g_sum/g_sumsq/g_ctr
// are reset by the LAST k_gemm CTA each launch -> deterministic across graph
// replays with no separate zeroing kernel.
__device__ __half g_Htp[(size_t)M_TOTAL * F];   // pre-BN linear output, fp16, 128MB
__device__ float g_sum[F];
__device__ float g_sumsq[F];
__device__ float g_scale[F];
__device__ float g_bias[F];
__device__ unsigned int g_ctr;

// ---------------- helpers ----------------------------------------------------
__device__ __forceinline__ uint32_t h2_bits(__half2 h) {
    uint32_t u;
    __builtin_memcpy(&u, &h, 4);
    return u;
}

__device__ __forceinline__ void cp_async16(void* smem_dst, const void* gsrc) {
    uint32_t s = (uint32_t)__cvta_generic_to_shared(smem_dst);
    asm volatile("cp.async.cg.shared.global [%0], [%1], 16;\n" :: "r"(s), "l"(gsrc));
}

// ---------------- K1: Ht = H @ W, fp16 mma, 2-stage cp.async pipeline --------
// CTA: 128 threads (4 warps). Each warp streams TPW tiles of 16 rows through a
// double-buffered fp32 staging area (cp.async, prefetch distance 1 tile).
// Consumed buffer is recycled as fp16 epilogue staging.
// TPW=16 (coarse): per-CTA prologue amortized — measured optimum.
// Tail: last-finishing CTA finalizes BN scale/bias; then every CTA signals
// griddepcontrol.launch_dependents so the PDL-launched stencil can overlap
// its prologue with this grid's drain.
// NOTE: strides MUST be >= 64 (k/col index spans 0..63); 72 additionally makes
// frag LDS.64, epilogue STS and the dense LDS.128 sweep all conflict-free.
#define TPW 16                      /* tiles (of 16 rows) per warp */
#define FSTRIDE 72                  /* floats */
#define WSTRIDE 72                  /* halves */

__global__ __launch_bounds__(128)
void k_gemm(const float* __restrict__ H, const float* __restrict__ W,
            const float* __restrict__ gamma, const float* __restrict__ beta) {
    __shared__ __half sWt[64 * WSTRIDE];          // 9.2KB
    __shared__ float sF[4][2][16 * FSTRIDE];      // 36.9KB
    __shared__ float sSum[F], sSq[F];
    __shared__ int sIsLast;

    const int tid  = threadIdx.x;
    const int warp = tid >> 5;
    const int lane = tid & 31;
    const int g    = lane >> 2;    // 0..7
    const int tg   = lane & 3;     // 0..3

    const size_t warpRow0 = ((size_t)blockIdx.x * 4 + warp) * (TPW * 16);

    auto stage = [&](int t, float* buf) {
        const float* src = H + (warpRow0 + (size_t)t * 16) * F;
#pragma unroll
        for (int r = 0; r < 8; r++) {
            int f   = lane + 32 * r;      // float4 chunk 0..127
            int row = f >> 4, c4 = f & 15;
            cp_async16(&buf[row * FSTRIDE + c4 * 4], src + (size_t)f * 4);
        }
        asm volatile("cp.async.commit_group;\n" ::);
    };

    // Kick off tile 0 before anything else
    stage(0, sF[warp][0]);

    if (tid < F) { sSum[tid] = 0.f; sSq[tid] = 0.f; }

    // Build Wt (fp16, transposed) in smem
    for (int idx = tid; idx < 64 * 64; idx += 128) {
        int k = idx >> 6, n = idx & 63;
        sWt[n * WSTRIDE + k] = __float2half(W[idx]);
    }
    __syncthreads();

    // Stat accumulators: cols (nt*8 + 2tg) and (+1)
    float s[8][2], q[8][2];
#pragma unroll
    for (int nt = 0; nt < 8; nt++) { s[nt][0] = s[nt][1] = q[nt][0] = q[nt][1] = 0.f; }

#pragma unroll 1
    for (int t = 0; t < TPW; t++) {
        float* buf = sF[warp][t & 1];
        if (t + 1 < TPW) {
            stage(t + 1, sF[warp][(t + 1) & 1]);
            asm volatile("cp.async.wait_group 1;\n" ::);
        } else {
            asm volatile("cp.async.wait_group 0;\n" ::);
        }
        __syncwarp();   // staged data visible warp-wide

        float acc[8][4];
#pragma unroll
        for (int nt = 0; nt < 8; nt++)
#pragma unroll
            for (int i = 0; i < 4; i++) acc[nt][i] = 0.f;

#pragma unroll
        for (int ks = 0; ks < 4; ks++) {
            const int kc = ks * 16 + 2 * tg;
            float2 f0 = *(const float2*)&buf[(g    ) * FSTRIDE + kc    ];
            float2 f1 = *(const float2*)&buf[(g + 8) * FSTRIDE + kc    ];
            float2 f2 = *(const float2*)&buf[(g    ) * FSTRIDE + kc + 8];
            float2 f3 = *(const float2*)&buf[(g + 8) * FSTRIDE + kc + 8];
            uint32_t a0 = h2_bits(__floats2half2_rn(f0.x, f0.y));
            uint32_t a1 = h2_bits(__floats2half2_rn(f1.x, f1.y));
            uint32_t a2 = h2_bits(__floats2half2_rn(f2.x, f2.y));
            uint32_t a3 = h2_bits(__floats2half2_rn(f3.x, f3.y));
#pragma unroll
            for (int nt = 0; nt < 8; nt++) {
                uint32_t b0 = *(const uint32_t*)&sWt[(nt * 8 + g) * WSTRIDE + kc    ];
                uint32_t b1 = *(const uint32_t*)&sWt[(nt * 8 + g) * WSTRIDE + kc + 8];
                asm volatile(
                    "mma.sync.aligned.m16n8k16.row.col.f32.f16.f16.f32 "
                    "{%0,%1,%2,%3}, {%4,%5,%6,%7}, {%8,%9}, {%0,%1,%2,%3};"
                    : "+f"(acc[nt][0]), "+f"(acc[nt][1]),
                      "+f"(acc[nt][2]), "+f"(acc[nt][3])
                    : "r"(a0), "r"(a1), "r"(a2), "r"(a3),
                      "r"(b0), "r"(b1));
            }
        }
        __syncwarp();   // fragment reads done; buffer can be recycled

        // Epilogue: stats + fp16 fragments -> recycled staging buffer
        __half* eb = (__half*)buf;
#pragma unroll
        for (int nt = 0; nt < 8; nt++) {
            int colb = nt * 8 + 2 * tg;
            float c0 = acc[nt][0], c1 = acc[nt][1];
            float c2 = acc[nt][2], c3 = acc[nt][3];
            *(__half2*)&eb[(g    ) * WSTRIDE + colb] = __floats2half2_rn(c0, c1);
            *(__half2*)&eb[(g + 8) * WSTRIDE + colb] = __floats2half2_rn(c2, c3);
            s[nt][0] += c0 + c2;           s[nt][1] += c1 + c3;
            q[nt][0] += c0 * c0 + c2 * c2; q[nt][1] += c1 * c1 + c3 * c3;
        }
        __syncwarp();

        // Dense store: 4 x (LDS.128 + STG.128) covering 16 rows x 128B
        __half* outp = g_Htp + (warpRow0 + (size_t)t * 16) * F;
#pragma unroll
        for (int r = 0; r < 4; r++) {
            int u   = lane + 32 * r;        // 16B unit index, 128 total
            int row = u >> 3, cu = u & 7;
            uint4 x = *(const uint4*)&eb[row * WSTRIDE + cu * 8];
            *(uint4*)&outp[(size_t)row * F + cu * 8] = x;
        }
        __syncwarp();   // epilogue reads done before cp.async refills this buffer
    }

    // Reduce stats: butterfly over g, smem atomics, 64 global atomics
#pragma unroll
    for (int off = 4; off < 32; off <<= 1) {
#pragma unroll
        for (int nt = 0; nt < 8; nt++) {
            s[nt][0] += __shfl_xor_sync(0xffffffffu, s[nt][0], off);
            s[nt][1] += __shfl_xor_sync(0xffffffffu, s[nt][1], off);
            q[nt][0] += __shfl_xor_sync(0xffffffffu, q[nt][0], off);
            q[nt][1] += __shfl_xor_sync(0xffffffffu, q[nt][1], off);
        }
    }
    if (lane < 4) {
#pragma unroll
        for (int nt = 0; nt < 8; nt++) {
            int c = nt * 8 + 2 * lane;
            atomicAdd(&sSum[c],     s[nt][0]);
            atomicAdd(&sSum[c + 1], s[nt][1]);
            atomicAdd(&sSq[c],      q[nt][0]);
            atomicAdd(&sSq[c + 1],  q[nt][1]);
        }
    }
    __syncthreads();
    if (tid < F) {
        atomicAdd(&g_sum[tid],   sSum[tid]);
        atomicAdd(&g_sumsq[tid], sSq[tid]);
    }

    // ---- last-CTA finalization (threadfence-reduction pattern) ----
    __threadfence();
    __syncthreads();
    if (tid == 0) {
        unsigned int c = atomicAdd(&g_ctr, 1u);
        sIsLast = (c == gridDim.x - 1);
    }
    __syncthreads();
    if (sIsLast && tid < F) {
        float sum = __ldcg(&g_sum[tid]);      // L2-coherent reads (bypass L1)
        float sq  = __ldcg(&g_sumsq[tid]);
        float inv_m = 1.f / (float)M_TOTAL;
        float mean = sum * inv_m;
        float var  = sq * inv_m - mean * mean;
        float is   = rsqrtf(var + 1e-5f);
        float sc   = gamma[tid] * is;
        g_scale[tid] = sc;
        g_bias[tid]  = beta[tid] - mean * sc;
        // Reset accumulators + counter for the next launch / graph replay
        g_sum[tid]   = 0.f;
        g_sumsq[tid] = 0.f;
        if (tid == 0) g_ctr = 0u;
    }

    // PDL: all global writes by this CTA are done — allow dependents.
    asm volatile("griddepcontrol.launch_dependents;" ::: "memory");
}

// ---------------- K3: BN + ReLU + normalized 3x3 stencil (fp16 in) -----------
// CTA: 288 threads = 18 cols (16 out + 2 halo) x 16 half4 chunks.
// Row tile = 16 (measured best); 2 output rows per __syncthreads (4 smem
// buffers), loads prefetched 2 ahead; dval hoisted. Launched via PDL: index
// setup happens before griddepcontrol.wait; dependent loads after.
__global__ __launch_bounds__(288, 4)
void k_stencil(float* __restrict__ out) {
    __shared__ float4 cs[4][18][16];

    const int tid   = threadIdx.x;
    const int chunk = tid & 15;      // 0..15 (4 channels each)
    const int colL  = tid >> 4;      // 0..17
    const int b     = blockIdx.z;
    const int j0    = blockIdx.x * 16;
    const int i0    = blockIdx.y * 16;
    const int j     = j0 - 1 + colL;
    const bool jin  = (j >= 0 && j < CDIM);
    const bool isOut = (colL >= 1 && colL <= 16);

    const int   rj  = 3 - (j == 0) - (j == CDIM - 1);
    const float d3v = rsqrtf(3.f * rj + 1e-5f);
    const float d2v = rsqrtf(2.f * rj + 1e-5f);

    const __half* base = g_Htp + (size_t)b * NPIX * F;

    // Wait for the producer grid (all Ht rows + scale/bias) before any
    // dependent load. Everything above is pure setup and overlaps the
    // producer's drain.
    asm volatile("griddepcontrol.wait;" ::: "memory");

    const float4 sc = *(const float4*)&g_scale[chunk * 4];
    const float4 bs = *(const float4*)&g_bias[chunk * 4];

    auto dsel = [&](int i) -> float {
        return (i == 0 || i == RDIM - 1) ? d2v : d3v;
    };
    auto rawload = [&](int i) -> uint2 {
        if (!jin || i < 0 || i >= RDIM) return make_uint2(0u, 0u);
        return *(const uint2*)&base[((size_t)i * CDIM + j) * F + chunk * 4];
    };
    auto bnrow = [&](uint2 rw, int i) -> float4 {
        if (!jin || i < 0 || i >= RDIM) return make_float4(0.f, 0.f, 0.f, 0.f);
        float2 f0 = __half22float2(*(__half2*)&rw.x);
        float2 f1 = __half22float2(*(__half2*)&rw.y);
        float d = dsel(i);
        float4 r;
        r.x = fmaxf(fmaf(f0.x, sc.x, bs.x), 0.f) * d;
        r.y = fmaxf(fmaf(f0.y, sc.y, bs.y), 0.f) * d;
        r.z = fmaxf(fmaf(f1.x, sc.z, bs.z), 0.f) * d;
        r.w = fmaxf(fmaf(f1.y, sc.w, bs.w), 0.f) * d;
        return r;
    };

    float4 p = bnrow(rawload(i0 - 1), i0 - 1);
    float4 c = bnrow(rawload(i0), i0);
    uint2 rn  = rawload(i0 + 1);
    uint2 rn2 = rawload(i0 + 2);
    int bb = 0;

    for (int r = 0; r < 8; r++) {
        const int i = i0 + 2 * r;
        uint2 rn3 = rawload(i + 3);
        uint2 rn4 = rawload(i + 4);
        float4 n  = bnrow(rn,  i + 1);
        float4 n2 = bnrow(rn2, i + 2);
        float4 v0, v1;
        v0.x = p.x + c.x + n.x;   v1.x = c.x + n.x + n2.x;
        v0.y = p.y + c.y + n.y;   v1.y = c.y + n.y + n2.y;
        v0.z = p.z + c.z + n.z;   v1.z = c.z + n.z + n2.z;
        v0.w = p.w + c.w + n.w;   v1.w = c.w + n.w + n2.w;
        cs[bb][colL][chunk]     = v0;
        cs[bb + 1][colL][chunk] = v1;
        __syncthreads();
        if (isOut) {
            float4 l0 = cs[bb][colL - 1][chunk];
            float4 r0 = cs[bb][colL + 1][chunk];
            float dc0 = dsel(i);
            float4 o0;
            o0.x = (l0.x + v0.x + r0.x) * dc0;
            o0.y = (l0.y + v0.y + r0.y) * dc0;
            o0.z = (l0.z + v0.z + r0.z) * dc0;
            o0.w = (l0.w + v0.w + r0.w) * dc0;
            *(float4*)&out[((size_t)b * NPIX + (size_t)i * CDIM + j) * F + chunk * 4] = o0;

            float4 l1 = cs[bb + 1][colL - 1][chunk];
            float4 r1 = cs[bb + 1][colL + 1][chunk];
            float dc1 = dsel(i + 1);
            float4 o1;
            o1.x = (l1.x + v1.x + r1.x) * dc1;
            o1.y = (l1.y + v1.y + r1.y) * dc1;
            o1.z = (l1.z + v1.z + r1.z) * dc1;
            o1.w = (l1.w + v1.w + r1.w) * dc1;
            *(float4*)&out[((size_t)b * NPIX + (size_t)(i + 1) * CDIM + j) * F + chunk * 4] = o1;
        }
        p = n; c = n2; rn = rn3; rn2 = rn4; bb ^= 2;
    }
}

// ---------------- launch ------------------------------------------------------
extern "C" void kernel_launch(void* const* d_in, const int* in_sizes, int n_in,
                              void* d_out, int out_size) {
    (void)in_sizes; (void)n_in; (void)out_size;
    const float* H     = (const float*)d_in[0];
    const float* W     = (const float*)d_in[1];
    const float* gamma = (const float*)d_in[2];
    const float* beta  = (const float*)d_in[3];
    float* out = (float*)d_out;

    const int rows_per_cta = 4 * TPW * 16;   // 1024
    k_gemm<<<M_TOTAL / rows_per_cta, 128>>>(H, W, gamma, beta);

    // PDL launch of the stencil: prologue overlaps k_gemm's drain.
    cudaLaunchConfig_t cfg = {};
    cfg.gridDim  = dim3(CDIM / 16, RDIM / 16, BATCH);
    cfg.blockDim = dim3(288, 1, 1);
    cfg.dynamicSmemBytes = 0;
    cfg.stream = 0;
    cudaLaunchAttribute attrs[1];
    attrs[0].id = cudaLaunchAttributeProgrammaticStreamSerialization;
    attrs[0].val.programmaticStreamSerializationAllowed = 1;
    cfg.attrs = attrs;
    cfg.numAttrs = 1;
    cudaLaunchKernelEx(&cfg, k_stencil, out);
}